// round 9
// baseline (speedup 1.0000x reference)
#include <cuda_runtime.h>
#include <math.h>

#define T_DIM 1024
#define NP    32
#define DP    8
#define NT    16
#define DT    16
#define O_DIM 256   // NT*DT
#define KTAP  3

// ---- packed f32x2 helpers (sm_10x FFMA2) ----
__device__ __forceinline__ unsigned long long pack2(float a, float b) {
    unsigned long long r;
    asm("mov.b64 %0, {%1, %2};" : "=l"(r) : "f"(a), "f"(b));
    return r;
}
__device__ __forceinline__ void unpack2(unsigned long long v, float& a, float& b) {
    asm("mov.b64 {%0, %1}, %2;" : "=f"(a), "=f"(b) : "l"(v));
}
__device__ __forceinline__ void ffma2(unsigned long long& d,
                                      unsigned long long a,
                                      unsigned long long b) {
    asm("fma.rn.f32x2 %0, %1, %2, %0;" : "+l"(d) : "l"(a), "l"(b));
}

__global__ __launch_bounds__(256, 3)
void caps_kernel(const float* __restrict__ x,
                 const float* __restrict__ K,
                 const float* __restrict__ bias,
                 const float* __restrict__ Bw,
                 float* __restrict__ out)
{
    const int bt  = blockIdx.x;            // b*T + t
    const int t   = bt & (T_DIM - 1);
    const int tid = threadIdx.x;
    const int pg  = tid & 7;               // p-group: p = pg*4 .. pg*4+3
    const int og  = tid >> 3;              // o-group: o = og*8 .. og*8+7
    const int n   = og >> 1;               // capsule index (o = n*16 + d)

    __shared__ float xwt[KTAP][DP][NP];    // conv window transposed [r][d][p], 3 KB
    __shared__ float sk[24 * O_DIM];       // conv weights staged once, 24 KB

    // ---- stage K cooperatively (coalesced LDG.128, 6 per thread)
    {
        const float4* Ks = (const float4*)K;
        float4* sks = (float4*)sk;
        #pragma unroll
        for (int i = 0; i < 6; i++)
            sks[tid + i * 256] = Ks[tid + i * 256];
    }

    // ---- stage x window (rows t-1,t,t+1; zero-pad at seq edges)
    {
        const float* xbase = x + (size_t)bt * (NP * DP);
        #pragma unroll
        for (int r = 0; r < KTAP; r++) {
            int tt = t + r - 1;
            float v = 0.f;
            if (tt >= 0 && tt < T_DIM) v = xbase[(r - 1) * (NP * DP) + tid];
            xwt[r][tid & 7][tid >> 3] = v;
        }
    }

    // ---- accumulators: U[4p][8o] as 16 f32x2 pairs, init with bias[o]
    unsigned long long acc[4][4];
    {
        float4 b0 = *(const float4*)(bias + og * 8);
        float4 b1 = *(const float4*)(bias + og * 8 + 4);
        unsigned long long p0 = pack2(b0.x, b0.y);
        unsigned long long p1 = pack2(b0.z, b0.w);
        unsigned long long p2 = pack2(b1.x, b1.y);
        unsigned long long p3 = pack2(b1.z, b1.w);
        #pragma unroll
        for (int pi = 0; pi < 4; pi++) {
            acc[pi][0] = p0; acc[pi][1] = p1; acc[pi][2] = p2; acc[pi][3] = p3;
        }
    }
    __syncthreads();

    // ---- conv: per (r,d): 1 broadcast LDS.128 (4 p's) + 2 LDS.128 (8 k's)
    #pragma unroll
    for (int r = 0; r < KTAP; r++) {
        #pragma unroll
        for (int d = 0; d < DP; d++) {
            float4 x4 = *(const float4*)&xwt[r][d][pg * 4];
            const float* kp = sk + (r * 8 + d) * O_DIM + og * 8;
            ulonglong2 ka = *(const ulonglong2*)(kp);      // k-pairs (0,1),(2,3)
            ulonglong2 kb = *(const ulonglong2*)(kp + 4);  // k-pairs (4,5),(6,7)
            unsigned long long xx;
            xx = pack2(x4.x, x4.x);
            ffma2(acc[0][0], xx, ka.x); ffma2(acc[0][1], xx, ka.y);
            ffma2(acc[0][2], xx, kb.x); ffma2(acc[0][3], xx, kb.y);
            xx = pack2(x4.y, x4.y);
            ffma2(acc[1][0], xx, ka.x); ffma2(acc[1][1], xx, ka.y);
            ffma2(acc[1][2], xx, kb.x); ffma2(acc[1][3], xx, kb.y);
            xx = pack2(x4.z, x4.z);
            ffma2(acc[2][0], xx, ka.x); ffma2(acc[2][1], xx, ka.y);
            ffma2(acc[2][2], xx, kb.x); ffma2(acc[2][3], xx, kb.y);
            xx = pack2(x4.w, x4.w);
            ffma2(acc[3][0], xx, ka.x); ffma2(acc[3][1], xx, ka.y);
            ffma2(acc[3][2], xx, kb.x); ffma2(acc[3][3], xx, kb.y);
        }
    }

    // ---- relu, unpack to u[pi][j]; local v partial over this thread's 4 p
    float u[4][8];
    float vloc[8];
    #pragma unroll
    for (int j = 0; j < 8; j++) vloc[j] = 0.f;
    #pragma unroll
    for (int pi = 0; pi < 4; pi++) {
        #pragma unroll
        for (int jp = 0; jp < 4; jp++) {
            float a, b;
            unpack2(acc[pi][jp], a, b);
            a = fmaxf(a, 0.f); b = fmaxf(b, 0.f);
            u[pi][2 * jp]     = a;
            u[pi][2 * jp + 1] = b;
            vloc[2 * jp]     += a;
            vloc[2 * jp + 1] += b;
        }
    }

    // ---- v[n][d] over all 32 p: butterfly across the 8 pg lanes
    #pragma unroll
    for (int k = 1; k <= 4; k <<= 1) {
        #pragma unroll
        for (int j = 0; j < 8; j++)
            vloc[j] += __shfl_xor_sync(0xffffffffu, vloc[j], k);
    }

    // ---- scores s[n][q] for this thread's 4 q; og-twin (xor 8) holds other 8 d's
    float s[4];
    #pragma unroll
    for (int qi = 0; qi < 4; qi++) {
        float a = 0.f;
        #pragma unroll
        for (int j = 0; j < 8; j++) a = fmaf(vloc[j], u[qi][j], a);
        a += __shfl_xor_sync(0xffffffffu, a, 8);
        s[qi] = a * 0.35355339059327373f;   // 1/sqrt(8)
    }

    // ---- softmax over the 32 q (4 local x 8 pg lanes; og twins duplicate)
    float m = fmaxf(fmaxf(s[0], s[1]), fmaxf(s[2], s[3]));
    #pragma unroll
    for (int k = 1; k <= 4; k <<= 1)
        m = fmaxf(m, __shfl_xor_sync(0xffffffffu, m, k));
    float e[4];
    float sum = 0.f;
    #pragma unroll
    for (int qi = 0; qi < 4; qi++) { e[qi] = __expf(s[qi] - m); sum += e[qi]; }
    #pragma unroll
    for (int k = 1; k <= 4; k <<= 1)
        sum += __shfl_xor_sync(0xffffffffu, sum, k);
    const float inv = 1.f / sum;

    // ---- mixing weights w[q] = C[n][q] + Bw[t][n][q] (coalesced LDG.128)
    float4 bw = *(const float4*)(Bw + (size_t)t * (NT * NP) + n * NP + pg * 4);
    float w0 = fmaf(e[0], inv, bw.x);
    float w1 = fmaf(e[1], inv, bw.y);
    float w2 = fmaf(e[2], inv, bw.z);
    float w3 = fmaf(e[3], inv, bw.w);

    // ---- out partials over local 4 q, then reduce-scatter over the 8 pg lanes
    float po[8];
    #pragma unroll
    for (int j = 0; j < 8; j++) {
        float a = w0 * u[0][j];
        a = fmaf(w1, u[1][j], a);
        a = fmaf(w2, u[2][j], a);
        a = fmaf(w3, u[3][j], a);
        po[j] = a;
    }
    #pragma unroll
    for (int k = 4; k >= 1; k >>= 1) {
        const int sel = pg & k;
        #pragma unroll
        for (int j = 0; j < k; j++) {
            float a = po[j], b = po[j + k];
            float snd = sel ? a : b;
            float rcv = __shfl_xor_sync(0xffffffffu, snd, k);
            po[j] = (sel ? b : a) + rcv;
        }
    }
    const float o_val = po[0];   // fully-summed out[n][d] for o = og*8+pg = tid

    // ---- squash over the 16 d-lanes of capsule n
    float sq = o_val * o_val;
    #pragma unroll
    for (int off = 1; off <= 8; off <<= 1)
        sq += __shfl_xor_sync(0xffffffffu, sq, off);
    float nrm = sqrtf(sq);
    out[(size_t)bt * O_DIM + tid] = (sq / (sq + 1.f)) * (o_val / (nrm + 1e-7f));
}

extern "C" void kernel_launch(void* const* d_in, const int* in_sizes, int n_in,
                              void* d_out, int out_size)
{
    const float* x    = (const float*)d_in[0];   // (8,1024,32,8)
    const float* K    = (const float*)d_in[1];   // (3,8,1,256)
    const float* bias = (const float*)d_in[2];   // (256,)
    const float* Bw   = (const float*)d_in[3];   // (1024,16,1,32)
    float* out = (float*)d_out;                  // (8,1024,16,16)

    const int B = in_sizes[0] / (T_DIM * NP * DP);   // 8
    caps_kernel<<<B * T_DIM, 256>>>(x, K, bias, Bw, out);
}

// round 10
// speedup vs baseline: 1.4789x; 1.4789x over previous
#include <cuda_runtime.h>
#include <math.h>

#define T_DIM 1024
#define NP    32
#define DP    8
#define NT    16
#define DT    16
#define O_DIM 256   // NT*DT
#define KTAP  3

// ---- packed f32x2 helpers (sm_10x FFMA2) ----
__device__ __forceinline__ unsigned long long pack2(float a, float b) {
    unsigned long long r;
    asm("mov.b64 %0, {%1, %2};" : "=l"(r) : "f"(a), "f"(b));
    return r;
}
__device__ __forceinline__ void unpack2(unsigned long long v, float& a, float& b) {
    asm("mov.b64 {%0, %1}, %2;" : "=f"(a), "=f"(b) : "l"(v));
}
__device__ __forceinline__ void ffma2(unsigned long long& d,
                                      unsigned long long a,
                                      unsigned long long b) {
    asm("fma.rn.f32x2 %0, %1, %2, %0;" : "+l"(d) : "l"(a), "l"(b));
}

__global__ __launch_bounds__(256, 2)   // REVERTED: give FFMA2 its register headroom back
void caps_kernel(const float* __restrict__ x,
                 const float* __restrict__ K,
                 const float* __restrict__ bias,
                 const float* __restrict__ Bw,
                 float* __restrict__ out)
{
    const int bt  = blockIdx.x;            // b*T + t
    const int t   = bt & (T_DIM - 1);
    const int tid = threadIdx.x;
    const int pg  = tid & 7;               // p-group: p = pg*4 .. pg*4+3
    const int og  = tid >> 3;              // o-group: o = og*8 .. og*8+7
    const int n   = og >> 1;               // capsule index (o = n*16 + d)

    __shared__ float xwt[KTAP][DP][NP];    // conv window transposed [r][d][p], 3 KB
    __shared__ float sk[24 * O_DIM];       // conv weights staged once, 24 KB

    // ---- stage K cooperatively (coalesced LDG.128, 6 per thread)
    {
        const float4* Ks = (const float4*)K;
        float4* sks = (float4*)sk;
        #pragma unroll
        for (int i = 0; i < 6; i++)
            sks[tid + i * 256] = Ks[tid + i * 256];
    }

    // ---- stage x window (rows t-1,t,t+1; zero-pad at seq edges)
    {
        const float* xbase = x + (size_t)bt * (NP * DP);
        #pragma unroll
        for (int r = 0; r < KTAP; r++) {
            int tt = t + r - 1;
            float v = 0.f;
            if (tt >= 0 && tt < T_DIM) v = xbase[(r - 1) * (NP * DP) + tid];
            xwt[r][tid & 7][tid >> 3] = v;
        }
    }

    // ---- accumulators: U[4p][8o] as 16 f32x2 pairs, init with bias[o]
    unsigned long long acc[4][4];
    {
        float4 b0 = *(const float4*)(bias + og * 8);
        float4 b1 = *(const float4*)(bias + og * 8 + 4);
        unsigned long long p0 = pack2(b0.x, b0.y);
        unsigned long long p1 = pack2(b0.z, b0.w);
        unsigned long long p2 = pack2(b1.x, b1.y);
        unsigned long long p3 = pack2(b1.z, b1.w);
        #pragma unroll
        for (int pi = 0; pi < 4; pi++) {
            acc[pi][0] = p0; acc[pi][1] = p1; acc[pi][2] = p2; acc[pi][3] = p3;
        }
    }
    __syncthreads();

    // ---- conv: per (r,d): 1 broadcast LDS.128 (4 p's) + 2 LDS.128 (8 k's)
    #pragma unroll
    for (int r = 0; r < KTAP; r++) {
        #pragma unroll
        for (int d = 0; d < DP; d++) {
            float4 x4 = *(const float4*)&xwt[r][d][pg * 4];
            const float* kp = sk + (r * 8 + d) * O_DIM + og * 8;
            ulonglong2 ka = *(const ulonglong2*)(kp);      // k-pairs (0,1),(2,3)
            ulonglong2 kb = *(const ulonglong2*)(kp + 4);  // k-pairs (4,5),(6,7)
            unsigned long long xx;
            xx = pack2(x4.x, x4.x);
            ffma2(acc[0][0], xx, ka.x); ffma2(acc[0][1], xx, ka.y);
            ffma2(acc[0][2], xx, kb.x); ffma2(acc[0][3], xx, kb.y);
            xx = pack2(x4.y, x4.y);
            ffma2(acc[1][0], xx, ka.x); ffma2(acc[1][1], xx, ka.y);
            ffma2(acc[1][2], xx, kb.x); ffma2(acc[1][3], xx, kb.y);
            xx = pack2(x4.z, x4.z);
            ffma2(acc[2][0], xx, ka.x); ffma2(acc[2][1], xx, ka.y);
            ffma2(acc[2][2], xx, kb.x); ffma2(acc[2][3], xx, kb.y);
            xx = pack2(x4.w, x4.w);
            ffma2(acc[3][0], xx, ka.x); ffma2(acc[3][1], xx, ka.y);
            ffma2(acc[3][2], xx, kb.x); ffma2(acc[3][3], xx, kb.y);
        }
    }

    // ---- relu, unpack to u[pi][j]; local v partial over this thread's 4 p
    float u[4][8];
    float vloc[8];
    #pragma unroll
    for (int j = 0; j < 8; j++) vloc[j] = 0.f;
    #pragma unroll
    for (int pi = 0; pi < 4; pi++) {
        #pragma unroll
        for (int jp = 0; jp < 4; jp++) {
            float a, b;
            unpack2(acc[pi][jp], a, b);
            a = fmaxf(a, 0.f); b = fmaxf(b, 0.f);
            u[pi][2 * jp]     = a;
            u[pi][2 * jp + 1] = b;
            vloc[2 * jp]     += a;
            vloc[2 * jp + 1] += b;
        }
    }

    // ---- v[n][d] over all 32 p: butterfly across the 8 pg lanes
    #pragma unroll
    for (int k = 1; k <= 4; k <<= 1) {
        #pragma unroll
        for (int j = 0; j < 8; j++)
            vloc[j] += __shfl_xor_sync(0xffffffffu, vloc[j], k);
    }

    // ---- scores s[n][q] for this thread's 4 q; og-twin (xor 8) holds other 8 d's
    float s[4];
    #pragma unroll
    for (int qi = 0; qi < 4; qi++) {
        float a = 0.f;
        #pragma unroll
        for (int j = 0; j < 8; j++) a = fmaf(vloc[j], u[qi][j], a);
        a += __shfl_xor_sync(0xffffffffu, a, 8);
        s[qi] = a * 0.35355339059327373f;   // 1/sqrt(8)
    }

    // ---- softmax over the 32 q (4 local x 8 pg lanes; og twins duplicate)
    float m = fmaxf(fmaxf(s[0], s[1]), fmaxf(s[2], s[3]));
    #pragma unroll
    for (int k = 1; k <= 4; k <<= 1)
        m = fmaxf(m, __shfl_xor_sync(0xffffffffu, m, k));
    float e[4];
    float sum = 0.f;
    #pragma unroll
    for (int qi = 0; qi < 4; qi++) { e[qi] = __expf(s[qi] - m); sum += e[qi]; }
    #pragma unroll
    for (int k = 1; k <= 4; k <<= 1)
        sum += __shfl_xor_sync(0xffffffffu, sum, k);
    const float inv = 1.f / sum;

    // ---- mixing weights w[q] = C[n][q] + Bw[t][n][q] (coalesced LDG.128)
    float4 bw = *(const float4*)(Bw + (size_t)t * (NT * NP) + n * NP + pg * 4);
    float w0 = fmaf(e[0], inv, bw.x);
    float w1 = fmaf(e[1], inv, bw.y);
    float w2 = fmaf(e[2], inv, bw.z);
    float w3 = fmaf(e[3], inv, bw.w);

    // ---- out partials over local 4 q, then reduce-scatter over the 8 pg lanes
    float po[8];
    #pragma unroll
    for (int j = 0; j < 8; j++) {
        float a = w0 * u[0][j];
        a = fmaf(w1, u[1][j], a);
        a = fmaf(w2, u[2][j], a);
        a = fmaf(w3, u[3][j], a);
        po[j] = a;
    }
    #pragma unroll
    for (int k = 4; k >= 1; k >>= 1) {
        const int sel = pg & k;
        #pragma unroll
        for (int j = 0; j < k; j++) {
            float a = po[j], b = po[j + k];
            float snd = sel ? a : b;
            float rcv = __shfl_xor_sync(0xffffffffu, snd, k);
            po[j] = (sel ? b : a) + rcv;
        }
    }
    const float o_val = po[0];   // fully-summed out[n][d] for o = og*8+pg = tid

    // ---- squash over the 16 d-lanes of capsule n
    float sq = o_val * o_val;
    #pragma unroll
    for (int off = 1; off <= 8; off <<= 1)
        sq += __shfl_xor_sync(0xffffffffu, sq, off);
    float nrm = sqrtf(sq);
    out[(size_t)bt * O_DIM + tid] = (sq / (sq + 1.f)) * (o_val / (nrm + 1e-7f));
}

extern "C" void kernel_launch(void* const* d_in, const int* in_sizes, int n_in,
                              void* d_out, int out_size)
{
    const float* x    = (const float*)d_in[0];   // (8,1024,32,8)
    const float* K    = (const float*)d_in[1];   // (3,8,1,256)
    const float* bias = (const float*)d_in[2];   // (256,)
    const float* Bw   = (const float*)d_in[3];   // (1024,16,1,32)
    float* out = (float*)d_out;                  // (8,1024,16,16)

    const int B = in_sizes[0] / (T_DIM * NP * DP);   // 8
    caps_kernel<<<B * T_DIM, 256>>>(x, K, bias, Bw, out);
}